// round 5
// baseline (speedup 1.0000x reference)
#include <cuda_runtime.h>
#include <cstdint>

// Problem dims (fixed for this instance)
#define BQ 64
#define TQ 256
#define DQ 300
#define HQ 256      // hidden
#define KQ 37       // tags
#define MBQ (TQ*BQ) // 16384 rows (t*B + b)

// ---------------- scratch (static device globals; no allocation) ----------------
__device__ float g_xgA[(size_t)MBQ * 1024];  // 64 MB  (forward-direction input gates)
__device__ float g_xgB[(size_t)MBQ * 1024];  // 64 MB  (backward-direction input gates)
__device__ float g_h0 [(size_t)MBQ * 512];   // 32 MB  (layer0 output, [fwd|bwd])
__device__ float g_h1 [(size_t)MBQ * 512];   // 32 MB  (layer1 output)
__device__ float g_em [(size_t)MBQ * KQ];    // 2.4 MB (emissions)
__device__ float g_llh[BQ];
__device__ unsigned g_bar[2];                // per-direction step barrier counters

// ---------------- helpers ----------------
__device__ __forceinline__ float sigf(float x)   { return 1.0f / (1.0f + __expf(-x)); }
__device__ __forceinline__ float tanh_f(float x) { return 2.0f / (1.0f + __expf(-2.0f * x)) - 1.0f; }

__global__ void reset_bar_kernel() {
    if (threadIdx.x < 2) g_bar[threadIdx.x] = 0u;
}

// ---------------- GEMM: C[M,N] = A(M,K) * Bw(N,K)^T + bias(N) ----------------
// GATHER: logical A row m = emb[text[(m&63)*256 + (m>>6)]]  (row length lda)
#define GBM 128
#define GBN 64
#define GBK 16

template <bool GATHER>
__global__ void __launch_bounds__(256)
gemm_nt_bias(const float* __restrict__ A, const int* __restrict__ textp,
             const float* __restrict__ Bw, const float* __restrict__ bias,
             float* __restrict__ C, int M, int N, int Kd, int lda)
{
    __shared__ float As[GBK * GBM];
    __shared__ float Bs[GBK * GBN];

    const int tid = threadIdx.x;
    const int m0  = blockIdx.y * GBM;
    const int n0  = blockIdx.x * GBN;
    const int tx  = tid & 15;       // 0..15 -> 4 cols each
    const int ty  = tid >> 4;       // 0..15 -> 8 rows each
    const int lr  = tid >> 2;       // 0..63 (A load row base)
    const int lkv = tid & 3;        // k-vec within tile

    float acc[8][4];
    #pragma unroll
    for (int i = 0; i < 8; ++i)
        #pragma unroll
        for (int j = 0; j < 4; ++j) acc[i][j] = 0.0f;

    const int Ktiles = (Kd + GBK - 1) / GBK;
    for (int kt = 0; kt < Ktiles; ++kt) {
        const int kb = kt * GBK;
        // ---- load A tile (128 rows x 16 k), transposed to As[k][m] ----
        #pragma unroll
        for (int p = 0; p < 2; ++p) {
            const int r = lr + p * 64;
            const int m = m0 + r;
            const int kg = kb + lkv * 4;
            float4 v = make_float4(0.f, 0.f, 0.f, 0.f);
            const float* rowp;
            if (GATHER) {
                const int bb = m & 63;
                const int tt = m >> 6;
                const int tok = textp[bb * TQ + tt];
                rowp = A + (size_t)tok * lda;
            } else {
                rowp = A + (size_t)m * lda;
            }
            if (kg + 3 < Kd) v = *(const float4*)(rowp + kg);   // Kd % 4 == 0 always here
            As[(lkv * 4 + 0) * GBM + r] = v.x;
            As[(lkv * 4 + 1) * GBM + r] = v.y;
            As[(lkv * 4 + 2) * GBM + r] = v.z;
            As[(lkv * 4 + 3) * GBM + r] = v.w;
        }
        // ---- load B tile (64 rows x 16 k), transposed to Bs[k][n] ----
        {
            const int n  = tid >> 2;
            const int kv = tid & 3;
            const int kg = kb + kv * 4;
            float4 v = make_float4(0.f, 0.f, 0.f, 0.f);
            if ((n0 + n) < N && (kg + 3) < Kd)
                v = *(const float4*)(Bw + (size_t)(n0 + n) * Kd + kg);
            Bs[(kv * 4 + 0) * GBN + n] = v.x;
            Bs[(kv * 4 + 1) * GBN + n] = v.y;
            Bs[(kv * 4 + 2) * GBN + n] = v.z;
            Bs[(kv * 4 + 3) * GBN + n] = v.w;
        }
        __syncthreads();
        // ---- compute ----
        #pragma unroll
        for (int k = 0; k < GBK; ++k) {
            float4 a0 = *(const float4*)&As[k * GBM + ty * 8];
            float4 a1 = *(const float4*)&As[k * GBM + ty * 8 + 4];
            float4 bv = *(const float4*)&Bs[k * GBN + tx * 4];
            float av[8] = {a0.x, a0.y, a0.z, a0.w, a1.x, a1.y, a1.z, a1.w};
            float bb4[4] = {bv.x, bv.y, bv.z, bv.w};
            #pragma unroll
            for (int i = 0; i < 8; ++i)
                #pragma unroll
                for (int j = 0; j < 4; ++j)
                    acc[i][j] = fmaf(av[i], bb4[j], acc[i][j]);
        }
        __syncthreads();
    }
    // ---- epilogue ----
    #pragma unroll
    for (int i = 0; i < 8; ++i) {
        const int m = m0 + ty * 8 + i;   // M % 128 == 0 -> always valid
        #pragma unroll
        for (int j = 0; j < 4; ++j) {
            const int n = n0 + tx * 4 + j;
            if (n < N) C[(size_t)m * N + n] = acc[i][j] + bias[n];
        }
    }
}

// ---------------- persistent bidirectional LSTM scan ----------------
// grid = 128 blocks: blocks [0,64) forward, [64,128) backward. 128 threads.
// Block owns 4 hidden units (all 4 gates) for all 64 batches.
// Thread (bg, u, ks): bg=tid>>3 (4 batches), u=(tid>>1)&3 (unit), ks=tid&1 (k half, interleaved).
__global__ void __launch_bounds__(128)
lstm_scan(const float* __restrict__ xgF, const float* __restrict__ xgBk,
          const float* __restrict__ WhhF, const float* __restrict__ WhhB,
          float* __restrict__ hout)
{
    const int dir = blockIdx.x >> 6;       // 0 fwd, 1 bwd
    const int blk = blockIdx.x & 63;
    const int u0  = blk * 4;
    const int tid = threadIdx.x;
    const int bg  = tid >> 3;
    const int u   = (tid >> 1) & 3;
    const int ks  = tid & 1;
    const int unit = u0 + u;
    const int dof  = dir ? 256 : 0;

    const float* xg  = dir ? xgBk : xgF;
    const float* Whh = dir ? WhhB : WhhF;

    __shared__ float Ws[16 * 264];   // rows r = g*4+uu, padded to 264 floats (conflict-free)
    for (int i = tid; i < 16 * 256; i += 128) {
        const int r = i >> 8, k = i & 255;
        const int g = r >> 2, uu = r & 3;
        Ws[r * 264 + k] = Whh[(size_t)(g * 256 + u0 + uu) * 256 + k];
    }
    __syncthreads();

    const float4* w0 = (const float4*)&Ws[(0 * 4 + u) * 264];
    const float4* w1 = (const float4*)&Ws[(1 * 4 + u) * 264];
    const float4* w2 = (const float4*)&Ws[(2 * 4 + u) * 264];
    const float4* w3 = (const float4*)&Ws[(3 * 4 + u) * 264];

    float cc[4] = {0.f, 0.f, 0.f, 0.f};

    for (int s = 0; s < TQ; ++s) {
        const int t = dir ? (TQ - 1 - s) : s;
        float acc[4][4];
        #pragma unroll
        for (int i = 0; i < 4; ++i)
            #pragma unroll
            for (int g = 0; g < 4; ++g) acc[i][g] = 0.0f;

        if (s > 0) {
            const int tp = dir ? (t + 1) : (t - 1);
            const float* hb = hout + (size_t)tp * BQ * 512 + dof;
            #pragma unroll 8
            for (int kk = 0; kk < 32; ++kk) {
                const int kv = kk * 2 + ks;      // float4 index 0..63 (interleaved halves)
                const float4 a0 = w0[kv];
                const float4 a1 = w1[kv];
                const float4 a2 = w2[kv];
                const float4 a3 = w3[kv];
                #pragma unroll
                for (int i = 0; i < 4; ++i) {
                    const int b = bg * 4 + i;
                    const float4 hv = __ldg((const float4*)(hb + (size_t)b * 512 + kv * 4));
                    acc[i][0] += hv.x * a0.x + hv.y * a0.y + hv.z * a0.z + hv.w * a0.w;
                    acc[i][1] += hv.x * a1.x + hv.y * a1.y + hv.z * a1.z + hv.w * a1.w;
                    acc[i][2] += hv.x * a2.x + hv.y * a2.y + hv.z * a2.z + hv.w * a2.w;
                    acc[i][3] += hv.x * a3.x + hv.y * a3.y + hv.z * a3.z + hv.w * a3.w;
                }
            }
        }
        // reduce the two interleaved k-halves (partner = tid^1)
        #pragma unroll
        for (int i = 0; i < 4; ++i)
            #pragma unroll
            for (int g = 0; g < 4; ++g)
                acc[i][g] += __shfl_xor_sync(0xffffffffu, acc[i][g], 1);

        const float* xgt = xg + (size_t)t * BQ * 1024;
        #pragma unroll
        for (int i = 0; i < 4; ++i) {
            const int b = bg * 4 + i;
            const float* xr = xgt + (size_t)b * 1024 + unit;
            const float zi = acc[i][0] + __ldg(xr + 0);
            const float zf = acc[i][1] + __ldg(xr + 256);
            const float zg = acc[i][2] + __ldg(xr + 512);
            const float zo = acc[i][3] + __ldg(xr + 768);
            const float ig = sigf(zi), fg = sigf(zf), gg = tanh_f(zg), og = sigf(zo);
            cc[i] = fg * cc[i] + ig * gg;
            const float hval = og * tanh_f(cc[i]);
            if (ks == 0) hout[((size_t)t * BQ + b) * 512 + dof + unit] = hval;
        }

        // per-direction inter-block barrier
        __threadfence();
        __syncthreads();
        if (tid == 0) {
            atomicAdd(&g_bar[dir], 1u);
            const unsigned target = (unsigned)(s + 1) * 64u;
            while (*((volatile unsigned*)&g_bar[dir]) < target) { }
        }
        __syncthreads();
    }
}

// ---------------- CRF: one block per batch ----------------
__global__ void __launch_bounds__(64)
crf_kernel(const int* __restrict__ text, const int* __restrict__ sbj,
           const float* __restrict__ em, const float* __restrict__ start_t,
           const float* __restrict__ end_t, const float* __restrict__ trans,
           float* __restrict__ llh)
{
    const int b   = blockIdx.x;
    const int tid = threadIdx.x;
    __shared__ float tr[KQ * KQ];
    __shared__ float sc[KQ];
    for (int i = tid; i < KQ * KQ; i += 64) tr[i] = trans[i];
    if (tid < KQ) sc[tid] = start_t[tid] + em[(size_t)b * KQ + tid];
    __syncthreads();

    for (int t = 1; t < TQ; ++t) {
        const int tok = text[b * TQ + t];          // uniform across block
        if (tok != 0) {
            float nv = 0.0f;
            if (tid < KQ) {
                float mx = -1e30f;
                #pragma unroll 1
                for (int j = 0; j < KQ; ++j) mx = fmaxf(mx, sc[j] + tr[j * KQ + tid]);
                float ssum = 0.0f;
                #pragma unroll 1
                for (int j = 0; j < KQ; ++j) ssum += __expf(sc[j] + tr[j * KQ + tid] - mx);
                nv = em[((size_t)t * BQ + b) * KQ + tid] + mx + __logf(ssum);
            }
            __syncthreads();
            if (tid < KQ) sc[tid] = nv;
            __syncthreads();
        }
    }

    if (tid == 0) {
        // logZ
        float mx = -1e30f;
        for (int k = 0; k < KQ; ++k) mx = fmaxf(mx, sc[k] + end_t[k]);
        float ssum = 0.0f;
        for (int k = 0; k < KQ; ++k) ssum += __expf(sc[k] + end_t[k] - mx);
        const float logZ = mx + __logf(ssum);
        // numerator (mask is a contiguous prefix: lengths >= T/2 >= 1)
        int tag0 = sbj[b * TQ + 0];
        float num = start_t[tag0] + em[(size_t)b * KQ + tag0];
        int prev = tag0, last = tag0;
        for (int t = 1; t < TQ; ++t) {
            if (text[b * TQ + t] != 0) {
                const int tg = sbj[b * TQ + t];
                num += em[((size_t)t * BQ + b) * KQ + tg] + tr[prev * KQ + tg];
                prev = tg; last = tg;
            }
        }
        num += end_t[last];
        llh[b] = num - logZ;
    }
}

// ---------------- finalize ----------------
__global__ void __launch_bounds__(256)
finalize_kernel(const int* __restrict__ text, const float* __restrict__ llh,
                float* __restrict__ out)
{
    __shared__ float sred[256];
    __shared__ float cred[256];
    const int tid = threadIdx.x;
    float s = 0.0f, c = 0.0f;
    for (int i = tid; i < BQ; i += 256) s += llh[i];
    for (int i = tid; i < BQ * TQ; i += 256) c += (text[i] != 0) ? 1.0f : 0.0f;
    sred[tid] = s; cred[tid] = c;
    __syncthreads();
    for (int off = 128; off > 0; off >>= 1) {
        if (tid < off) { sred[tid] += sred[tid + off]; cred[tid] += cred[tid + off]; }
        __syncthreads();
    }
    if (tid == 0) out[0] = -(sred[0] / cred[0]);
}

// ---------------- launch ----------------
extern "C" void kernel_launch(void* const* d_in, const int* in_sizes, int n_in,
                              void* d_out, int out_size)
{
    const int*   text  = (const int*)  d_in[0];
    const int*   sbj   = (const int*)  d_in[1];
    const float* emb   = (const float*)d_in[2];
    const float* Wih0f = (const float*)d_in[3];
    const float* Whh0f = (const float*)d_in[4];
    const float* b0f   = (const float*)d_in[5];
    const float* Wih0b = (const float*)d_in[6];
    const float* Whh0b = (const float*)d_in[7];
    const float* b0b   = (const float*)d_in[8];
    const float* Wih1f = (const float*)d_in[9];
    const float* Whh1f = (const float*)d_in[10];
    const float* b1f   = (const float*)d_in[11];
    const float* Wih1b = (const float*)d_in[12];
    const float* Whh1b = (const float*)d_in[13];
    const float* b1b   = (const float*)d_in[14];
    const float* W_sbj = (const float*)d_in[15];
    const float* b_sbj = (const float*)d_in[16];
    const float* st_t  = (const float*)d_in[17];
    const float* en_t  = (const float*)d_in[18];
    const float* trans = (const float*)d_in[19];
    float* out = (float*)d_out;

    float *xgA, *xgB, *h0, *h1, *em, *llh;
    cudaGetSymbolAddress((void**)&xgA, g_xgA);
    cudaGetSymbolAddress((void**)&xgB, g_xgB);
    cudaGetSymbolAddress((void**)&h0,  g_h0);
    cudaGetSymbolAddress((void**)&h1,  g_h1);
    cudaGetSymbolAddress((void**)&em,  g_em);
    cudaGetSymbolAddress((void**)&llh, g_llh);

    const dim3 gGemmFull(1024 / GBN, MBQ / GBM);   // (16, 128)
    const dim3 gGemmEm((KQ + GBN - 1) / GBN, MBQ / GBM); // (1, 128)

    // layer 0 input projections (fused embedding gather)
    gemm_nt_bias<true><<<gGemmFull, 256>>>(emb, text, Wih0f, b0f, xgA, MBQ, 1024, DQ, DQ);
    gemm_nt_bias<true><<<gGemmFull, 256>>>(emb, text, Wih0b, b0b, xgB, MBQ, 1024, DQ, DQ);
    reset_bar_kernel<<<1, 32>>>();
    lstm_scan<<<128, 128>>>(xgA, xgB, Whh0f, Whh0b, h0);

    // layer 1 input projections
    gemm_nt_bias<false><<<gGemmFull, 256>>>(h0, nullptr, Wih1f, b1f, xgA, MBQ, 1024, 512, 512);
    gemm_nt_bias<false><<<gGemmFull, 256>>>(h0, nullptr, Wih1b, b1b, xgB, MBQ, 1024, 512, 512);
    reset_bar_kernel<<<1, 32>>>();
    lstm_scan<<<128, 128>>>(xgA, xgB, Whh1f, Whh1b, h1);

    // emissions
    gemm_nt_bias<false><<<gGemmEm, 256>>>(h1, nullptr, W_sbj, b_sbj, em, MBQ, KQ, 512, 512);

    // CRF + reduce
    crf_kernel<<<BQ, 64>>>(text, sbj, em, st_t, en_t, trans, llh);
    finalize_kernel<<<1, 256>>>(text, llh, out);
}

// round 6
// speedup vs baseline: 1.9467x; 1.9467x over previous
#include <cuda_runtime.h>
#include <cstdint>

// Problem dims (fixed for this instance)
#define BQ 64
#define TQ 256
#define DQ 300
#define HQ 256      // hidden
#define KQ 37       // tags
#define MBQ (TQ*BQ) // 16384 rows (t*B + b)

// ---------------- scratch (static device globals; no allocation) ----------------
__device__ float g_xgA[(size_t)MBQ * 1024];  // 64 MB  (forward-direction input gates)
__device__ float g_xgB[(size_t)MBQ * 1024];  // 64 MB  (backward-direction input gates)
__device__ float g_h0 [(size_t)MBQ * 512];   // 32 MB  (layer0 output, [fwd|bwd])
__device__ float g_h1 [(size_t)MBQ * 512];   // 32 MB  (layer1 output)
__device__ float g_em [(size_t)MBQ * KQ];    // 2.4 MB (emissions)
__device__ float g_llh[BQ];
__device__ unsigned g_bar[64];               // per-direction step barrier counters (padded)

// ---------------- helpers ----------------
__device__ __forceinline__ float sigf(float x)   { return 1.0f / (1.0f + __expf(-x)); }
__device__ __forceinline__ float tanh_f(float x) { return 2.0f / (1.0f + __expf(-2.0f * x)) - 1.0f; }

__global__ void reset_bar_kernel() {
    if (threadIdx.x < 64) g_bar[threadIdx.x] = 0u;
}

// ---------------- GEMM: C[M,N] = A(M,K) * Bw(N,K)^T + bias(N) ----------------
// 128x128 tile, 16-k, 256 threads, 8x8 microtile (split-half layout).
// GATHER: logical A row m = emb[text[(m&63)*256 + (m>>6)]]
#define GBM 128
#define GBN 128
#define GBK 16

template <bool GATHER>
__global__ void __launch_bounds__(256)
gemm_nt_bias(const float* __restrict__ A, const int* __restrict__ textp,
             const float* __restrict__ Bw, const float* __restrict__ bias,
             float* __restrict__ C, int M, int N, int Kd, int lda)
{
    __shared__ float As[GBK * GBM];
    __shared__ float Bs[GBK * GBN];

    const int tid = threadIdx.x;
    const int m0  = blockIdx.y * GBM;
    const int n0  = blockIdx.x * GBN;
    const int tx  = tid & 15;       // 0..15
    const int ty  = tid >> 4;       // 0..15
    const int lrow = tid >> 1;      // 0..127 (load row)
    const int lkv0 = (tid & 1) * 2; // {0, 2}

    float acc[8][8];
    #pragma unroll
    for (int i = 0; i < 8; ++i)
        #pragma unroll
        for (int j = 0; j < 8; ++j) acc[i][j] = 0.0f;

    // A source row pointer (row index fixed per thread across k-tiles)
    const float* arow_p;
    {
        const int m = m0 + lrow;
        if (GATHER) {
            const int bb = m & 63;
            const int tt = m >> 6;
            const int tok = textp[bb * TQ + tt];
            arow_p = A + (size_t)tok * lda;
        } else {
            arow_p = A + (size_t)m * lda;
        }
    }
    const int nrow = n0 + lrow;
    const float* brow_p = Bw + (size_t)nrow * Kd;
    const bool bvalid = nrow < N;

    const int Ktiles = (Kd + GBK - 1) / GBK;
    for (int kt = 0; kt < Ktiles; ++kt) {
        const int kb = kt * GBK;
        #pragma unroll
        for (int q = 0; q < 2; ++q) {
            const int kv = lkv0 + q;
            const int kg = kb + kv * 4;
            float4 va = make_float4(0.f, 0.f, 0.f, 0.f);
            float4 vb = make_float4(0.f, 0.f, 0.f, 0.f);
            if (kg + 3 < Kd) {
                va = *(const float4*)(arow_p + kg);
                if (bvalid) vb = *(const float4*)(brow_p + kg);
            }
            As[(kv * 4 + 0) * GBM + lrow] = va.x;
            As[(kv * 4 + 1) * GBM + lrow] = va.y;
            As[(kv * 4 + 2) * GBM + lrow] = va.z;
            As[(kv * 4 + 3) * GBM + lrow] = va.w;
            Bs[(kv * 4 + 0) * GBN + lrow] = vb.x;
            Bs[(kv * 4 + 1) * GBN + lrow] = vb.y;
            Bs[(kv * 4 + 2) * GBN + lrow] = vb.z;
            Bs[(kv * 4 + 3) * GBN + lrow] = vb.w;
        }
        __syncthreads();
        #pragma unroll
        for (int k = 0; k < GBK; ++k) {
            const float4 a0 = *(const float4*)&As[k * GBM + ty * 4];
            const float4 a1 = *(const float4*)&As[k * GBM + 64 + ty * 4];
            const float4 b0 = *(const float4*)&Bs[k * GBN + tx * 4];
            const float4 b1 = *(const float4*)&Bs[k * GBN + 64 + tx * 4];
            const float av[8] = {a0.x, a0.y, a0.z, a0.w, a1.x, a1.y, a1.z, a1.w};
            const float bv[8] = {b0.x, b0.y, b0.z, b0.w, b1.x, b1.y, b1.z, b1.w};
            #pragma unroll
            for (int i = 0; i < 8; ++i)
                #pragma unroll
                for (int j = 0; j < 8; ++j)
                    acc[i][j] = fmaf(av[i], bv[j], acc[i][j]);
        }
        __syncthreads();
    }
    // epilogue: split-half mapping. m half: i<4 -> ty*4+i ; i>=4 -> 64+ty*4+i-4
    #pragma unroll
    for (int i = 0; i < 8; ++i) {
        const int mi = (i < 4) ? (ty * 4 + i) : (64 + ty * 4 + (i - 4));
        const int m  = m0 + mi;   // M % 128 == 0 -> always valid
        #pragma unroll
        for (int j = 0; j < 8; ++j) {
            const int nj = (j < 4) ? (tx * 4 + j) : (64 + tx * 4 + (j - 4));
            const int n  = n0 + nj;
            if (n < N) C[(size_t)m * N + n] = acc[i][j] + bias[n];
        }
    }
}

// ---------------- persistent bidirectional LSTM scan ----------------
// grid = 128 blocks: [0,64) fwd, [64,128) bwd. 256 threads.
// Block owns 4 hidden units (all 4 gates) for all 64 batches.
// Thread (bg,u,ks): bg=tid>>4 (4 batches each), u=(tid>>2)&3, ks=tid&3 (k quarter).
// h_prev is staged into smem each step (coalesced), weights live in smem.
#define LSTM_SMEM (64 * 65 * 16 + 16 * 264 * 4)   // hs (float4[64][65]) + Ws

__global__ void __launch_bounds__(256)
lstm_scan(const float* __restrict__ xgF, const float* __restrict__ xgBk,
          const float* __restrict__ WhhF, const float* __restrict__ WhhB,
          float* __restrict__ hout)
{
    extern __shared__ char sm_raw[];
    float4* hs = (float4*)sm_raw;                         // [64][65]
    float*  Ws = (float*)(sm_raw + 64 * 65 * 16);         // [16][264]

    const int dir = blockIdx.x >> 6;
    const int blk = blockIdx.x & 63;
    const int u0  = blk * 4;
    const int tid = threadIdx.x;
    const int bg  = tid >> 4;         // 0..15
    const int u   = (tid >> 2) & 3;
    const int ks  = tid & 3;
    const int unit = u0 + u;
    const int dof  = dir ? 256 : 0;

    const float* xg  = dir ? xgBk : xgF;
    const float* Whh = dir ? WhhB : WhhF;
    unsigned* bar = &g_bar[dir * 32];

    for (int i = tid; i < 16 * 256; i += 256) {
        const int r = i >> 8, k = i & 255;
        const int g = r >> 2, uu = r & 3;
        Ws[r * 264 + k] = Whh[(size_t)(g * 256 + u0 + uu) * 256 + k];
    }
    __syncthreads();

    const float4* w0 = (const float4*)&Ws[(0 * 4 + u) * 264];
    const float4* w1 = (const float4*)&Ws[(1 * 4 + u) * 264];
    const float4* w2 = (const float4*)&Ws[(2 * 4 + u) * 264];
    const float4* w3 = (const float4*)&Ws[(3 * 4 + u) * 264];

    float cc[4] = {0.f, 0.f, 0.f, 0.f};

    for (int s = 0; s < TQ; ++s) {
        const int t = dir ? (TQ - 1 - s) : s;

        // prefetch xg early (independent of h_{t-1}) -- only the ks==0 lanes need it
        float xv[4][4];
        if (ks == 0) {
            const float* xgt = xg + (size_t)t * BQ * 1024;
            #pragma unroll
            for (int i = 0; i < 4; ++i) {
                const float* xr = xgt + (size_t)(bg * 4 + i) * 1024 + unit;
                xv[i][0] = __ldg(xr + 0);
                xv[i][1] = __ldg(xr + 256);
                xv[i][2] = __ldg(xr + 512);
                xv[i][3] = __ldg(xr + 768);
            }
        }

        float acc[4][4];
        #pragma unroll
        for (int i = 0; i < 4; ++i)
            #pragma unroll
            for (int g = 0; g < 4; ++g) acc[i][g] = 0.0f;

        if (s > 0) {
            // ---- stage h_prev (64 x 256 of this direction) into smem, coalesced ----
            const int tp = dir ? (t + 1) : (t - 1);
            const float* hb = hout + (size_t)tp * BQ * 512 + dof;
            #pragma unroll
            for (int j = 0; j < 16; ++j) {
                const int idx = tid + j * 256;
                const int b = idx >> 6, kv = idx & 63;
                hs[b * 65 + kv] = __ldg((const float4*)(hb + (size_t)b * 512 + kv * 4));
            }
            __syncthreads();
            // ---- mat-vec from smem ----
            #pragma unroll 4
            for (int kk = 0; kk < 16; ++kk) {
                const int kv = kk * 4 + ks;
                const float4 a0 = w0[kv];
                const float4 a1 = w1[kv];
                const float4 a2 = w2[kv];
                const float4 a3 = w3[kv];
                #pragma unroll
                for (int i = 0; i < 4; ++i) {
                    const float4 hv = hs[(bg * 4 + i) * 65 + kv];
                    acc[i][0] += hv.x * a0.x + hv.y * a0.y + hv.z * a0.z + hv.w * a0.w;
                    acc[i][1] += hv.x * a1.x + hv.y * a1.y + hv.z * a1.z + hv.w * a1.w;
                    acc[i][2] += hv.x * a2.x + hv.y * a2.y + hv.z * a2.z + hv.w * a2.w;
                    acc[i][3] += hv.x * a3.x + hv.y * a3.y + hv.z * a3.z + hv.w * a3.w;
                }
            }
        }
        // reduce the 4 interleaved k-quarters (lanes tid^1, tid^2)
        #pragma unroll
        for (int i = 0; i < 4; ++i)
            #pragma unroll
            for (int g = 0; g < 4; ++g) {
                acc[i][g] += __shfl_xor_sync(0xffffffffu, acc[i][g], 1);
                acc[i][g] += __shfl_xor_sync(0xffffffffu, acc[i][g], 2);
            }

        if (ks == 0) {
            #pragma unroll
            for (int i = 0; i < 4; ++i) {
                const int b = bg * 4 + i;
                const float zi = acc[i][0] + xv[i][0];
                const float zf = acc[i][1] + xv[i][1];
                const float zg = acc[i][2] + xv[i][2];
                const float zo = acc[i][3] + xv[i][3];
                const float ig = sigf(zi), fg = sigf(zf), gg = tanh_f(zg), og = sigf(zo);
                cc[i] = fg * cc[i] + ig * gg;
                hout[((size_t)t * BQ + b) * 512 + dof + unit] = og * tanh_f(cc[i]);
            }
        }

        // per-direction inter-block barrier
        __threadfence();
        __syncthreads();
        if (tid == 0) {
            atomicAdd(bar, 1u);
            const unsigned target = (unsigned)(s + 1) * 64u;
            while (*((volatile unsigned*)bar) < target) { }
        }
        __syncthreads();
    }
}

// ---------------- CRF: one block per batch ----------------
__global__ void __launch_bounds__(64)
crf_kernel(const int* __restrict__ text, const int* __restrict__ sbj,
           const float* __restrict__ em, const float* __restrict__ start_t,
           const float* __restrict__ end_t, const float* __restrict__ trans,
           float* __restrict__ llh)
{
    const int b   = blockIdx.x;
    const int tid = threadIdx.x;
    __shared__ float tr[KQ * KQ];
    __shared__ float sc[KQ];
    for (int i = tid; i < KQ * KQ; i += 64) tr[i] = trans[i];
    if (tid < KQ) sc[tid] = start_t[tid] + em[(size_t)b * KQ + tid];
    __syncthreads();

    for (int t = 1; t < TQ; ++t) {
        const int tok = text[b * TQ + t];          // uniform across block
        if (tok != 0) {
            float nv = 0.0f;
            if (tid < KQ) {
                float mx = -1e30f;
                #pragma unroll 1
                for (int j = 0; j < KQ; ++j) mx = fmaxf(mx, sc[j] + tr[j * KQ + tid]);
                float ssum = 0.0f;
                #pragma unroll 1
                for (int j = 0; j < KQ; ++j) ssum += __expf(sc[j] + tr[j * KQ + tid] - mx);
                nv = em[((size_t)t * BQ + b) * KQ + tid] + mx + __logf(ssum);
            }
            __syncthreads();
            if (tid < KQ) sc[tid] = nv;
            __syncthreads();
        }
    }

    if (tid == 0) {
        // logZ
        float mx = -1e30f;
        for (int k = 0; k < KQ; ++k) mx = fmaxf(mx, sc[k] + end_t[k]);
        float ssum = 0.0f;
        for (int k = 0; k < KQ; ++k) ssum += __expf(sc[k] + end_t[k] - mx);
        const float logZ = mx + __logf(ssum);
        // numerator (mask is a contiguous prefix: lengths >= T/2 >= 1)
        int tag0 = sbj[b * TQ + 0];
        float num = start_t[tag0] + em[(size_t)b * KQ + tag0];
        int prev = tag0, last = tag0;
        for (int t = 1; t < TQ; ++t) {
            if (text[b * TQ + t] != 0) {
                const int tg = sbj[b * TQ + t];
                num += em[((size_t)t * BQ + b) * KQ + tg] + tr[prev * KQ + tg];
                prev = tg; last = tg;
            }
        }
        num += end_t[last];
        llh[b] = num - logZ;
    }
}

// ---------------- finalize ----------------
__global__ void __launch_bounds__(256)
finalize_kernel(const int* __restrict__ text, const float* __restrict__ llh,
                float* __restrict__ out)
{
    __shared__ float sred[256];
    __shared__ float cred[256];
    const int tid = threadIdx.x;
    float s = 0.0f, c = 0.0f;
    for (int i = tid; i < BQ; i += 256) s += llh[i];
    for (int i = tid; i < BQ * TQ; i += 256) c += (text[i] != 0) ? 1.0f : 0.0f;
    sred[tid] = s; cred[tid] = c;
    __syncthreads();
    for (int off = 128; off > 0; off >>= 1) {
        if (tid < off) { sred[tid] += sred[tid + off]; cred[tid] += cred[tid + off]; }
        __syncthreads();
    }
    if (tid == 0) out[0] = -(sred[0] / cred[0]);
}

// ---------------- launch ----------------
extern "C" void kernel_launch(void* const* d_in, const int* in_sizes, int n_in,
                              void* d_out, int out_size)
{
    const int*   text  = (const int*)  d_in[0];
    const int*   sbj   = (const int*)  d_in[1];
    const float* emb   = (const float*)d_in[2];
    const float* Wih0f = (const float*)d_in[3];
    const float* Whh0f = (const float*)d_in[4];
    const float* b0f   = (const float*)d_in[5];
    const float* Wih0b = (const float*)d_in[6];
    const float* Whh0b = (const float*)d_in[7];
    const float* b0b   = (const float*)d_in[8];
    const float* Wih1f = (const float*)d_in[9];
    const float* Whh1f = (const float*)d_in[10];
    const float* b1f   = (const float*)d_in[11];
    const float* Wih1b = (const float*)d_in[12];
    const float* Whh1b = (const float*)d_in[13];
    const float* b1b   = (const float*)d_in[14];
    const float* W_sbj = (const float*)d_in[15];
    const float* b_sbj = (const float*)d_in[16];
    const float* st_t  = (const float*)d_in[17];
    const float* en_t  = (const float*)d_in[18];
    const float* trans = (const float*)d_in[19];
    float* out = (float*)d_out;

    float *xgA, *xgB, *h0, *h1, *em, *llh;
    cudaGetSymbolAddress((void**)&xgA, g_xgA);
    cudaGetSymbolAddress((void**)&xgB, g_xgB);
    cudaGetSymbolAddress((void**)&h0,  g_h0);
    cudaGetSymbolAddress((void**)&h1,  g_h1);
    cudaGetSymbolAddress((void**)&em,  g_em);
    cudaGetSymbolAddress((void**)&llh, g_llh);

    cudaFuncSetAttribute(lstm_scan, cudaFuncAttributeMaxDynamicSharedMemorySize, LSTM_SMEM);

    const dim3 gGemmFull(1024 / GBN, MBQ / GBM);          // (8, 128)
    const dim3 gGemmEm(1, MBQ / GBM);                     // (1, 128)  N=37

    // layer 0 input projections (fused embedding gather)
    gemm_nt_bias<true><<<gGemmFull, 256>>>(emb, text, Wih0f, b0f, xgA, MBQ, 1024, DQ, DQ);
    gemm_nt_bias<true><<<gGemmFull, 256>>>(emb, text, Wih0b, b0b, xgB, MBQ, 1024, DQ, DQ);
    reset_bar_kernel<<<1, 64>>>();
    lstm_scan<<<128, 256, LSTM_SMEM>>>(xgA, xgB, Whh0f, Whh0b, h0);

    // layer 1 input projections
    gemm_nt_bias<false><<<gGemmFull, 256>>>(h0, nullptr, Wih1f, b1f, xgA, MBQ, 1024, 512, 512);
    gemm_nt_bias<false><<<gGemmFull, 256>>>(h0, nullptr, Wih1b, b1b, xgB, MBQ, 1024, 512, 512);
    reset_bar_kernel<<<1, 64>>>();
    lstm_scan<<<128, 256, LSTM_SMEM>>>(xgA, xgB, Whh1f, Whh1b, h1);

    // emissions
    gemm_nt_bias<false><<<gGemmEm, 256>>>(h1, nullptr, W_sbj, b_sbj, em, MBQ, KQ, 512, 512);

    // CRF + reduce
    crf_kernel<<<BQ, 64>>>(text, sbj, em, st_t, en_t, trans, llh);
    finalize_kernel<<<1, 256>>>(text, llh, out);
}

// round 7
// speedup vs baseline: 2.0135x; 1.0343x over previous
#include <cuda_runtime.h>
#include <cstdint>

// Problem dims (fixed for this instance)
#define BQ 64
#define TQ 256
#define DQ 300
#define HQ 256      // hidden
#define KQ 37       // tags
#define MBQ (TQ*BQ) // 16384 rows (t*B + b)

typedef unsigned long long ull;

// ---------------- scratch (static device globals; no allocation) ----------------
__device__ float g_xgA[(size_t)MBQ * 1024];  // 64 MB
__device__ float g_xgB[(size_t)MBQ * 1024];  // 64 MB
__device__ float g_h0 [(size_t)MBQ * 512];   // 32 MB
__device__ float g_h1 [(size_t)MBQ * 512];   // 32 MB
__device__ float g_em [(size_t)MBQ * KQ];    // 2.4 MB
__device__ float g_llh[BQ];
__device__ unsigned g_bar[64];               // per-direction barrier counters (padded)

// ---------------- helpers ----------------
__device__ __forceinline__ float sigf(float x)   { return 1.0f / (1.0f + __expf(-x)); }
__device__ __forceinline__ float tanh_f(float x) { return 2.0f / (1.0f + __expf(-2.0f * x)) - 1.0f; }

__device__ __forceinline__ ull ffma2(ull a, ull b, ull c) {
    ull d;
    asm("fma.rn.f32x2 %0, %1, %2, %3;" : "=l"(d) : "l"(a), "l"(b), "l"(c));
    return d;
}
__device__ __forceinline__ ull pk2(float lo, float hi) {
    ull r;
    asm("mov.b64 %0, {%1, %2};" : "=l"(r) : "f"(lo), "f"(hi));
    return r;
}
__device__ __forceinline__ float2 unpk2(ull v) {
    float2 r;
    asm("mov.b64 {%0, %1}, %2;" : "=f"(r.x), "=f"(r.y) : "l"(v));
    return r;
}

__global__ void reset_bar_kernel() {
    if (threadIdx.x < 64) g_bar[threadIdx.x] = 0u;
}

// ---------------- GEMM: C[M,N] = A(M,K) * Bw(N,K)^T + bias(N) ----------------
// 128x128 tile, 16-k, 256 threads, 8x8 microtile via FFMA2 (j-paired accumulators).
#define GBM 128
#define GBN 128
#define GBK 16

template <bool GATHER>
__global__ void __launch_bounds__(256)
gemm_nt_bias(const float* __restrict__ A, const int* __restrict__ textp,
             const float* __restrict__ Bw, const float* __restrict__ bias,
             float* __restrict__ C, int M, int N, int Kd, int lda)
{
    __shared__ float As[GBK * GBM];
    __shared__ float Bs[GBK * GBN];

    const int tid = threadIdx.x;
    const int m0  = blockIdx.y * GBM;
    const int n0  = blockIdx.x * GBN;
    const int tx  = tid & 15;
    const int ty  = tid >> 4;
    const int lrow = tid >> 1;
    const int lkv0 = (tid & 1) * 2;

    ull acc2[8][4];
    #pragma unroll
    for (int i = 0; i < 8; ++i)
        #pragma unroll
        for (int j = 0; j < 4; ++j) acc2[i][j] = 0ull;

    const float* arow_p;
    {
        const int m = m0 + lrow;
        if (GATHER) {
            const int bb = m & 63;
            const int tt = m >> 6;
            const int tok = textp[bb * TQ + tt];
            arow_p = A + (size_t)tok * lda;
        } else {
            arow_p = A + (size_t)m * lda;
        }
    }
    const int nrow = n0 + lrow;
    const float* brow_p = Bw + (size_t)nrow * Kd;
    const bool bvalid = nrow < N;

    const int Ktiles = (Kd + GBK - 1) / GBK;
    for (int kt = 0; kt < Ktiles; ++kt) {
        const int kb = kt * GBK;
        #pragma unroll
        for (int q = 0; q < 2; ++q) {
            const int kv = lkv0 + q;
            const int kg = kb + kv * 4;
            float4 va = make_float4(0.f, 0.f, 0.f, 0.f);
            float4 vb = make_float4(0.f, 0.f, 0.f, 0.f);
            if (kg + 3 < Kd) {
                va = *(const float4*)(arow_p + kg);
                if (bvalid) vb = *(const float4*)(brow_p + kg);
            }
            As[(kv * 4 + 0) * GBM + lrow] = va.x;
            As[(kv * 4 + 1) * GBM + lrow] = va.y;
            As[(kv * 4 + 2) * GBM + lrow] = va.z;
            As[(kv * 4 + 3) * GBM + lrow] = va.w;
            Bs[(kv * 4 + 0) * GBN + lrow] = vb.x;
            Bs[(kv * 4 + 1) * GBN + lrow] = vb.y;
            Bs[(kv * 4 + 2) * GBN + lrow] = vb.z;
            Bs[(kv * 4 + 3) * GBN + lrow] = vb.w;
        }
        __syncthreads();
        #pragma unroll
        for (int k = 0; k < GBK; ++k) {
            const float4 a0 = *(const float4*)&As[k * GBM + ty * 4];
            const float4 a1 = *(const float4*)&As[k * GBM + 64 + ty * 4];
            const ulonglong2 b0 = *(const ulonglong2*)&Bs[k * GBN + tx * 4];
            const ulonglong2 b1 = *(const ulonglong2*)&Bs[k * GBN + 64 + tx * 4];
            const ull bv2[4] = {b0.x, b0.y, b1.x, b1.y};
            const float av[8] = {a0.x, a0.y, a0.z, a0.w, a1.x, a1.y, a1.z, a1.w};
            #pragma unroll
            for (int i = 0; i < 8; ++i) {
                const ull av2 = pk2(av[i], av[i]);
                #pragma unroll
                for (int j = 0; j < 4; ++j)
                    acc2[i][j] = ffma2(av2, bv2[j], acc2[i][j]);
            }
        }
        __syncthreads();
    }
    // epilogue: cols for acc2[i][j] = pair (2j, 2j+1) of split-half mapping
    #pragma unroll
    for (int i = 0; i < 8; ++i) {
        const int mi = (i < 4) ? (ty * 4 + i) : (64 + ty * 4 + (i - 4));
        const int m  = m0 + mi;
        #pragma unroll
        for (int j = 0; j < 4; ++j) {
            const float2 v = unpk2(acc2[i][j]);
            const int c0 = (j < 2) ? (tx * 4 + 2 * j) : (64 + tx * 4 + 2 * (j - 2));
            if (c0 + 0 + n0 < N) C[(size_t)m * N + n0 + c0 + 0] = v.x + bias[n0 + c0 + 0];
            if (c0 + 1 + n0 < N) C[(size_t)m * N + n0 + c0 + 1] = v.y + bias[n0 + c0 + 1];
        }
    }
}

// ---------------- persistent bidirectional LSTM scan ----------------
// grid = 128 blocks: [0,64) fwd, [64,128) bwd. 256 threads.
// Block owns 4 hidden units x 64 batches. Thread (bgrp,u,ks):
//   bgrp=tid>>5 (8 batches), u=(tid>>3)&3 (unit), ks=tid&7 (k-slice, 8 float4s).
// k-pairs packed in f32x2 lanes; reduce across ks via 3 shfl levels, then lanes.
#define LSTM_SMEM (64 * 65 * 16 + 16 * 264 * 4)   // hs float4[64][65] + Ws[16][264]

__global__ void __launch_bounds__(256)
lstm_scan(const float* __restrict__ xgF, const float* __restrict__ xgBk,
          const float* __restrict__ WhhF, const float* __restrict__ WhhB,
          float* __restrict__ hout)
{
    extern __shared__ char sm_raw[];
    float4* hs = (float4*)sm_raw;                     // [64][65]
    float*  Ws = (float*)(sm_raw + 64 * 65 * 16);     // [16][264]

    const int dir = blockIdx.x >> 6;
    const int blk = blockIdx.x & 63;
    const int u0  = blk * 4;
    const int tid = threadIdx.x;
    const int bgrp = tid >> 5;        // 0..7 -> batches bgrp*8 .. +7
    const int u    = (tid >> 3) & 3;
    const int ks   = tid & 7;
    const int unit = u0 + u;
    const int dof  = dir ? 256 : 0;

    const float* xg  = dir ? xgBk : xgF;
    const float* Whh = dir ? WhhB : WhhF;
    unsigned* bar = &g_bar[dir * 32];

    for (int i = tid; i < 16 * 256; i += 256) {
        const int r = i >> 8, k = i & 255;
        const int g = r >> 2, uu = r & 3;
        Ws[r * 264 + k] = Whh[(size_t)(g * 256 + u0 + uu) * 256 + k];
    }
    __syncthreads();

    const float4* wp0 = (const float4*)&Ws[(0 * 4 + u) * 264];
    const float4* wp1 = (const float4*)&Ws[(1 * 4 + u) * 264];
    const float4* wp2 = (const float4*)&Ws[(2 * 4 + u) * 264];
    const float4* wp3 = (const float4*)&Ws[(3 * 4 + u) * 264];

    float cc[8];
    #pragma unroll
    for (int i = 0; i < 8; ++i) cc[i] = 0.0f;

    for (int s = 0; s < TQ; ++s) {
        const int t = dir ? (TQ - 1 - s) : s;

        // prefetch xg early (only ks==0 lanes consume it)
        float xv[8][4];
        if (ks == 0) {
            const float* xgt = xg + (size_t)t * BQ * 1024;
            #pragma unroll
            for (int i = 0; i < 8; ++i) {
                const float* xr = xgt + (size_t)(bgrp * 8 + i) * 1024 + unit;
                xv[i][0] = __ldg(xr + 0);
                xv[i][1] = __ldg(xr + 256);
                xv[i][2] = __ldg(xr + 512);
                xv[i][3] = __ldg(xr + 768);
            }
        }

        ull acc2[8][4];
        #pragma unroll
        for (int i = 0; i < 8; ++i)
            #pragma unroll
            for (int g = 0; g < 4; ++g) acc2[i][g] = 0ull;

        if (s > 0) {
            // stage h_prev (coalesced) into smem
            const int tp = dir ? (t + 1) : (t - 1);
            const float* hb = hout + (size_t)tp * BQ * 512 + dof;
            #pragma unroll
            for (int j = 0; j < 16; ++j) {
                const int idx = tid + j * 256;
                const int b = idx >> 6, kv = idx & 63;
                hs[b * 65 + kv] = __ldg((const float4*)(hb + (size_t)b * 512 + kv * 4));
            }
            __syncthreads();
            // mat-vec from smem, k-pairs in f32x2 lanes
            #pragma unroll
            for (int q = 0; q < 8; ++q) {
                const int kv = ks + q * 8;
                const ulonglong2 w0 = *(const ulonglong2*)(wp0 + kv);
                const ulonglong2 w1 = *(const ulonglong2*)(wp1 + kv);
                const ulonglong2 w2 = *(const ulonglong2*)(wp2 + kv);
                const ulonglong2 w3 = *(const ulonglong2*)(wp3 + kv);
                #pragma unroll
                for (int i = 0; i < 8; ++i) {
                    const ulonglong2 h2 = *(const ulonglong2*)&hs[(bgrp * 8 + i) * 65 + kv];
                    acc2[i][0] = ffma2(h2.x, w0.x, acc2[i][0]);
                    acc2[i][0] = ffma2(h2.y, w0.y, acc2[i][0]);
                    acc2[i][1] = ffma2(h2.x, w1.x, acc2[i][1]);
                    acc2[i][1] = ffma2(h2.y, w1.y, acc2[i][1]);
                    acc2[i][2] = ffma2(h2.x, w2.x, acc2[i][2]);
                    acc2[i][2] = ffma2(h2.y, w2.y, acc2[i][2]);
                    acc2[i][3] = ffma2(h2.x, w3.x, acc2[i][3]);
                    acc2[i][3] = ffma2(h2.y, w3.y, acc2[i][3]);
                }
            }
        }

        // reduce: f32x2 lanes, then ks (shfl xor 1,2,4 within warp; lane = u*8+ks)
        float accf[8][4];
        #pragma unroll
        for (int i = 0; i < 8; ++i)
            #pragma unroll
            for (int g = 0; g < 4; ++g) {
                const float2 v = unpk2(acc2[i][g]);
                float a = v.x + v.y;
                a += __shfl_xor_sync(0xffffffffu, a, 1);
                a += __shfl_xor_sync(0xffffffffu, a, 2);
                a += __shfl_xor_sync(0xffffffffu, a, 4);
                accf[i][g] = a;
            }

        if (ks == 0) {
            #pragma unroll
            for (int i = 0; i < 8; ++i) {
                const int b = bgrp * 8 + i;
                const float zi = accf[i][0] + xv[i][0];
                const float zf = accf[i][1] + xv[i][1];
                const float zg = accf[i][2] + xv[i][2];
                const float zo = accf[i][3] + xv[i][3];
                const float ig = sigf(zi), fg = sigf(zf), gg = tanh_f(zg), og = sigf(zo);
                cc[i] = fg * cc[i] + ig * gg;
                hout[((size_t)t * BQ + b) * 512 + dof + unit] = og * tanh_f(cc[i]);
            }
        }

        // per-direction inter-block barrier
        __threadfence();
        __syncthreads();
        if (tid == 0) {
            atomicAdd(bar, 1u);
            const unsigned target = (unsigned)(s + 1) * 64u;
            while (*((volatile unsigned*)bar) < target) { }
        }
        __syncthreads();
    }
}

// ---------------- CRF: one block per batch ----------------
__global__ void __launch_bounds__(64)
crf_kernel(const int* __restrict__ text, const int* __restrict__ sbj,
           const float* __restrict__ em, const float* __restrict__ start_t,
           const float* __restrict__ end_t, const float* __restrict__ trans,
           float* __restrict__ llh)
{
    const int b   = blockIdx.x;
    const int tid = threadIdx.x;
    __shared__ float tr[KQ * KQ];
    __shared__ float sc[KQ];
    for (int i = tid; i < KQ * KQ; i += 64) tr[i] = trans[i];
    if (tid < KQ) sc[tid] = start_t[tid] + em[(size_t)b * KQ + tid];
    __syncthreads();

    for (int t = 1; t < TQ; ++t) {
        const int tok = text[b * TQ + t];
        if (tok != 0) {
            float nv = 0.0f;
            if (tid < KQ) {
                float mx = -1e30f;
                #pragma unroll 1
                for (int j = 0; j < KQ; ++j) mx = fmaxf(mx, sc[j] + tr[j * KQ + tid]);
                float ssum = 0.0f;
                #pragma unroll 1
                for (int j = 0; j < KQ; ++j) ssum += __expf(sc[j] + tr[j * KQ + tid] - mx);
                nv = em[((size_t)t * BQ + b) * KQ + tid] + mx + __logf(ssum);
            }
            __syncthreads();
            if (tid < KQ) sc[tid] = nv;
            __syncthreads();
        }
    }

    if (tid == 0) {
        float mx = -1e30f;
        for (int k = 0; k < KQ; ++k) mx = fmaxf(mx, sc[k] + end_t[k]);
        float ssum = 0.0f;
        for (int k = 0; k < KQ; ++k) ssum += __expf(sc[k] + end_t[k] - mx);
        const float logZ = mx + __logf(ssum);
        int tag0 = sbj[b * TQ + 0];
        float num = start_t[tag0] + em[(size_t)b * KQ + tag0];
        int prev = tag0, last = tag0;
        for (int t = 1; t < TQ; ++t) {
            if (text[b * TQ + t] != 0) {
                const int tg = sbj[b * TQ + t];
                num += em[((size_t)t * BQ + b) * KQ + tg] + tr[prev * KQ + tg];
                prev = tg; last = tg;
            }
        }
        num += end_t[last];
        llh[b] = num - logZ;
    }
}

// ---------------- finalize ----------------
__global__ void __launch_bounds__(256)
finalize_kernel(const int* __restrict__ text, const float* __restrict__ llh,
                float* __restrict__ out)
{
    __shared__ float sred[256];
    __shared__ float cred[256];
    const int tid = threadIdx.x;
    float s = 0.0f, c = 0.0f;
    for (int i = tid; i < BQ; i += 256) s += llh[i];
    for (int i = tid; i < BQ * TQ; i += 256) c += (text[i] != 0) ? 1.0f : 0.0f;
    sred[tid] = s; cred[tid] = c;
    __syncthreads();
    for (int off = 128; off > 0; off >>= 1) {
        if (tid < off) { sred[tid] += sred[tid + off]; cred[tid] += cred[tid + off]; }
        __syncthreads();
    }
    if (tid == 0) out[0] = -(sred[0] / cred[0]);
}

// ---------------- launch ----------------
extern "C" void kernel_launch(void* const* d_in, const int* in_sizes, int n_in,
                              void* d_out, int out_size)
{
    const int*   text  = (const int*)  d_in[0];
    const int*   sbj   = (const int*)  d_in[1];
    const float* emb   = (const float*)d_in[2];
    const float* Wih0f = (const float*)d_in[3];
    const float* Whh0f = (const float*)d_in[4];
    const float* b0f   = (const float*)d_in[5];
    const float* Wih0b = (const float*)d_in[6];
    const float* Whh0b = (const float*)d_in[7];
    const float* b0b   = (const float*)d_in[8];
    const float* Wih1f = (const float*)d_in[9];
    const float* Whh1f = (const float*)d_in[10];
    const float* b1f   = (const float*)d_in[11];
    const float* Wih1b = (const float*)d_in[12];
    const float* Whh1b = (const float*)d_in[13];
    const float* b1b   = (const float*)d_in[14];
    const float* W_sbj = (const float*)d_in[15];
    const float* b_sbj = (const float*)d_in[16];
    const float* st_t  = (const float*)d_in[17];
    const float* en_t  = (const float*)d_in[18];
    const float* trans = (const float*)d_in[19];
    float* out = (float*)d_out;

    float *xgA, *xgB, *h0, *h1, *em, *llh;
    cudaGetSymbolAddress((void**)&xgA, g_xgA);
    cudaGetSymbolAddress((void**)&xgB, g_xgB);
    cudaGetSymbolAddress((void**)&h0,  g_h0);
    cudaGetSymbolAddress((void**)&h1,  g_h1);
    cudaGetSymbolAddress((void**)&em,  g_em);
    cudaGetSymbolAddress((void**)&llh, g_llh);

    cudaFuncSetAttribute(lstm_scan, cudaFuncAttributeMaxDynamicSharedMemorySize, LSTM_SMEM);

    const dim3 gGemmFull(1024 / GBN, MBQ / GBM);   // (8, 128)
    const dim3 gGemmEm(1, MBQ / GBM);              // (1, 128)  N=37

    gemm_nt_bias<true><<<gGemmFull, 256>>>(emb, text, Wih0f, b0f, xgA, MBQ, 1024, DQ, DQ);
    gemm_nt_bias<true><<<gGemmFull, 256>>>(emb, text, Wih0b, b0b, xgB, MBQ, 1024, DQ, DQ);
    reset_bar_kernel<<<1, 64>>>();
    lstm_scan<<<128, 256, LSTM_SMEM>>>(xgA, xgB, Whh0f, Whh0b, h0);

    gemm_nt_bias<false><<<gGemmFull, 256>>>(h0, nullptr, Wih1f, b1f, xgA, MBQ, 1024, 512, 512);
    gemm_nt_bias<false><<<gGemmFull, 256>>>(h0, nullptr, Wih1b, b1b, xgB, MBQ, 1024, 512, 512);
    reset_bar_kernel<<<1, 64>>>();
    lstm_scan<<<128, 256, LSTM_SMEM>>>(xgA, xgB, Whh1f, Whh1b, h1);

    gemm_nt_bias<false><<<gGemmEm, 256>>>(h1, nullptr, W_sbj, b_sbj, em, MBQ, KQ, 512, 512);

    crf_kernel<<<BQ, 64>>>(text, sbj, em, st_t, en_t, trans, llh);
    finalize_kernel<<<1, 256>>>(text, llh, out);
}